// round 15
// baseline (speedup 1.0000x reference)
#include <cuda_runtime.h>
#include <cuda_fp16.h>
#include <cuda_fp8.h>
#include <math.h>
#include <float.h>

#define NN    50000
#define EE    800000
#define ELNUM 850000          // EE + NN self loops
#define FIN   16
#define HIDD  64
#define NHEAD 4
#define CC    64
#define HC    256             // NHEAD*CC
#define GG    64
#define NEG   0.2f

#define SCAN_B    1024
#define SCAN_NBLK ((NN + SCAN_B - 1) / SCAN_B)   // 49

#define KP        (HIDD / 2)   // 32 k-pairs
#define MMA_GRID  296
#define NTILES    (NN / 16)    // 3125
#define MSG_STRIDE 272         // 16B-aligned, 4-bank row shift -> conflict-free

// ---------------- scratch (device globals; no allocation) ----------------
__device__ int      g_batch[NN];
__device__ int      g_deg[NN];
__device__ int      g_cursor[NN];
__device__ int      g_rowptr[NN + 1];
__device__ int      g_bsum[SCAN_NBLK];
__device__ int      g_csr_src[ELNUM];
__device__ unsigned g_amax[3][NHEAD];                      // encoded global max of as, per layer
__device__ __align__(16) __half   g_hf [NN * HIDD];        // fp16 node features (GEMM A)
__device__ __align__(16) unsigned g_wtp[3 * KP * HC];      // per-layer W^T k-pair-packed half2
__device__ __align__(16) unsigned g_wap[3 * KP * 8];       // per-layer [Wᵀasrc|Wᵀadst] half2
__device__ __align__(16) unsigned char g_hw8[(size_t)NN * HC]; // h @ W^T as e4m3 [N, 256]
__device__ __align__(16) float    g_as [NN * NHEAD];       // a_src . h  per node
__device__ __align__(16) float    g_ad [NN * NHEAD];       // a_dst . h  per node
__device__ float g_pool[GG * HIDD];
__device__ float g_cnt [GG];

// monotone float<->uint encoding for atomicMax on signed floats
__device__ __forceinline__ unsigned enc_f(float f) {
    unsigned u = __float_as_uint(f);
    return (u & 0x80000000u) ? ~u : (u | 0x80000000u);
}
__device__ __forceinline__ float dec_f(unsigned k) {
    return (k & 0x80000000u) ? __uint_as_float(k & 0x7fffffffu)
                             : __uint_as_float(~k);
}

// shared-memory int64-vs-int32 consensus probe (first 64 values of ei row 0)
#define IS64_PROBE(EI_PTR, OUT)                                     \
    __shared__ int s_is64;                                          \
    if (threadIdx.x < 32) {                                         \
        const int* p_ = (const int*)(EI_PTR);                       \
        int bad_ = (p_[2 * threadIdx.x + 1] != 0);                  \
        unsigned b_ = __ballot_sync(0xffffffffu, bad_);             \
        if (threadIdx.x == 0) s_is64 = (b_ == 0u);                  \
    }                                                               \
    __syncthreads();                                                \
    int OUT = s_is64;

// ---------------- zero / degree / CSR ----------------
__global__ void k_zero() {
    int i = blockIdx.x * blockDim.x + threadIdx.x;
    if (i < NN) { g_deg[i] = 1; g_cursor[i] = 0; }   // deg=1: self loop
    if (i < GG * HIDD) g_pool[i] = 0.f;
    if (i < GG) g_cnt[i] = 0.f;
}

__global__ void k_deg(const void* ei, const void* batch) {
    IS64_PROBE(ei, is64);
    int i = blockIdx.x * blockDim.x + threadIdx.x;
    if (i < EE) {
        int d = is64 ? (int)((const long long*)ei)[EE + i]
                     : ((const int*)ei)[EE + i];
        atomicAdd(&g_deg[d], 1);
    }
    if (i < NN) {
        g_batch[i] = is64 ? (int)((const long long*)batch)[i]
                          : ((const int*)batch)[i];
    }
}

__global__ void k_scan1() {
    __shared__ int ws[32];
    int b = blockIdx.x, tid = threadIdx.x;
    int i = b * SCAN_B + tid;
    int lane = tid & 31, w = tid >> 5;
    int x = (i < NN) ? g_deg[i] : 0;
#pragma unroll
    for (int o = 1; o < 32; o <<= 1) {
        int y = __shfl_up_sync(0xffffffffu, x, o);
        if (lane >= o) x += y;
    }
    if (lane == 31) ws[w] = x;
    __syncthreads();
    if (w == 0) {
        int y = ws[lane];
#pragma unroll
        for (int o = 1; o < 32; o <<= 1) {
            int z = __shfl_up_sync(0xffffffffu, y, o);
            if (lane >= o) y += z;
        }
        ws[lane] = y;
    }
    __syncthreads();
    int incl = x + (w > 0 ? ws[w - 1] : 0);
    if (i < NN) g_rowptr[i + 1] = incl;
    if (tid == SCAN_B - 1) g_bsum[b] = incl;
}

__global__ void k_scanfix() {
    int i = blockIdx.x * blockDim.x + threadIdx.x;
    if (i >= NN) return;
    int b = i >> 10;
    int off = 0;
    for (int j = 0; j < b; j++) off += g_bsum[j];
    g_rowptr[i + 1] += off;
    if (i == 0) g_rowptr[0] = 0;
}

__global__ void k_fill(const void* ei) {
    IS64_PROBE(ei, is64);
    int i = blockIdx.x * blockDim.x + threadIdx.x;
    if (i >= ELNUM) return;
    int s, d;
    if (i < EE) {
        if (is64) {
            s = (int)((const long long*)ei)[i];
            d = (int)((const long long*)ei)[EE + i];
        } else {
            s = ((const int*)ei)[i];
            d = ((const int*)ei)[EE + i];
        }
    } else {
        s = d = i - EE;   // self loop
    }
    int pos = g_rowptr[d] + atomicAdd(&g_cursor[d], 1);
    g_csr_src[pos] = s;
}

// ---------------- compute kernels ----------------
__global__ void k_lin_in(const float* __restrict__ x, const float* __restrict__ W,
                         const float* __restrict__ b) {
    int i = blockIdx.x * blockDim.x + threadIdx.x;
    if (i >= NN * HIDD) return;
    int n = i / HIDD, c = i % HIDD;
    const float* xr = x + n * FIN;
    const float* wr = W + c * FIN;
    float s = b[c];
#pragma unroll
    for (int k = 0; k < FIN; k++) s += xr[k] * wr[k];
    g_hf[i] = __float2half(s);
}

// prepack W -> k-pair half2 (per-layer buffer) + alpha cols + zero amax[layer]
__global__ void k_wpack(const float* __restrict__ W,
                        const float* __restrict__ asrc,
                        const float* __restrict__ adst, int layer) {
    int i = blockIdx.x * blockDim.x + threadIdx.x;
    if (i < KP * HC) {
        int kp = i >> 8, n = i & 255;
        __half2 v = __floats2half2_rn(W[n * HIDD + 2 * kp], W[n * HIDD + 2 * kp + 1]);
        g_wtp[layer * KP * HC + i] = *(unsigned*)&v;
    } else if (i < KP * HC + 256) {
        int j = i - KP * HC;          // [0,256)
        int n8 = j >> 5, kp = j & 31; // n8: 0-3 as heads, 4-7 ad heads
        int h = n8 & 3;
        const float* a = (n8 >= 4) ? adst : asrc;
        float w0 = 0.f, w1 = 0.f;
#pragma unroll
        for (int c = 0; c < CC; c++) {
            float av = a[h * CC + c];
            const float* wr = W + (h * CC + c) * HIDD;
            w0 += av * wr[2 * kp];
            w1 += av * wr[2 * kp + 1];
        }
        __half2 v = __floats2half2_rn(w0, w1);
        g_wap[layer * KP * 8 + kp * 8 + n8] = *(unsigned*)&v;
    } else if (i < KP * HC + 256 + NHEAD) {
        g_amax[layer][i - (KP * HC + 256)] = 0u;   // < enc(-FLT_MAX)
    }
}

// Tensor-core GEMM + alpha columns + running global alpha-src max.
// A-tile staged in smem once per block (kills 8x redundant L1 traffic).
__global__ void __launch_bounds__(256) k_mma(int layer) {
    int t = threadIdx.x;
    int w = t >> 5, lane = t & 31;
    int g = lane >> 2, tg = lane & 3;
    const unsigned* wtp = g_wtp + layer * KP * HC;
    const unsigned* wap = g_wap + layer * KP * 8;

    unsigned bf[4][4][2];
#pragma unroll
    for (int kc = 0; kc < 4; kc++)
#pragma unroll
        for (int j = 0; j < 4; j++) {
            int n = w * 32 + j * 8 + g;
            bf[kc][j][0] = wtp[(kc * 8 + tg) * HC + n];
            bf[kc][j][1] = wtp[(kc * 8 + 4 + tg) * HC + n];
        }
    unsigned bfa[4][2];
#pragma unroll
    for (int kc = 0; kc < 4; kc++) {
        bfa[kc][0] = wap[(kc * 8 + tg) * 8 + g];
        bfa[kc][1] = wap[(kc * 8 + 4 + tg) * 8 + g];
    }

    float mx0 = -FLT_MAX, mx1 = -FLT_MAX;

    __shared__ __align__(16) unsigned char sh_msg[16 * MSG_STRIDE];
    __shared__ unsigned sh_a[16][36];   // stride 36 -> conflict-free fragment reads
    const unsigned* hfu = (const unsigned*)g_hf;

    for (int tile = blockIdx.x; tile < NTILES; tile += gridDim.x) {
        int n0 = tile * 16;

        // cooperative A-tile load: 16 rows x 32 uint (2KB), coalesced
#pragma unroll
        for (int idx = t; idx < 16 * 32; idx += 256) {
            int r = idx >> 5, c = idx & 31;
            sh_a[r][c] = hfu[(n0 + r) * 32 + c];
        }
        __syncthreads();

        unsigned af[4][4];
#pragma unroll
        for (int kc = 0; kc < 4; kc++) {
            int kb2 = kc * 8;
            af[kc][0] = sh_a[g][kb2 + tg];
            af[kc][1] = sh_a[g + 8][kb2 + tg];
            af[kc][2] = sh_a[g][kb2 + 4 + tg];
            af[kc][3] = sh_a[g + 8][kb2 + 4 + tg];
        }

        float c[4][4];
#pragma unroll
        for (int j = 0; j < 4; j++) { c[j][0] = c[j][1] = c[j][2] = c[j][3] = 0.f; }
#pragma unroll
        for (int kc = 0; kc < 4; kc++)
#pragma unroll
            for (int j = 0; j < 4; j++)
                asm volatile(
                    "mma.sync.aligned.m16n8k16.row.col.f32.f16.f16.f32 "
                    "{%0,%1,%2,%3}, {%4,%5,%6,%7}, {%8,%9}, {%0,%1,%2,%3};"
                    : "+f"(c[j][0]), "+f"(c[j][1]), "+f"(c[j][2]), "+f"(c[j][3])
                    : "r"(af[kc][0]), "r"(af[kc][1]), "r"(af[kc][2]), "r"(af[kc][3]),
                      "r"(bf[kc][j][0]), "r"(bf[kc][j][1]));

        float cal[4] = {0.f, 0.f, 0.f, 0.f};
        if (w == 0) {
#pragma unroll
            for (int kc = 0; kc < 4; kc++)
                asm volatile(
                    "mma.sync.aligned.m16n8k16.row.col.f32.f16.f16.f32 "
                    "{%0,%1,%2,%3}, {%4,%5,%6,%7}, {%8,%9}, {%0,%1,%2,%3};"
                    : "+f"(cal[0]), "+f"(cal[1]), "+f"(cal[2]), "+f"(cal[3])
                    : "r"(af[kc][0]), "r"(af[kc][1]), "r"(af[kc][2]), "r"(af[kc][3]),
                      "r"(bfa[kc][0]), "r"(bfa[kc][1]));
        }

#pragma unroll
        for (int j = 0; j < 4; j++) {
            int col = w * 32 + j * 8 + tg * 2;
            __nv_fp8x2_storage_t s01 = __nv_cvt_float2_to_fp8x2(
                make_float2(c[j][0], c[j][1]), __NV_SATFINITE, __NV_E4M3);
            __nv_fp8x2_storage_t s23 = __nv_cvt_float2_to_fp8x2(
                make_float2(c[j][2], c[j][3]), __NV_SATFINITE, __NV_E4M3);
            *(unsigned short*)&sh_msg[g * MSG_STRIDE + col]       = s01;
            *(unsigned short*)&sh_msg[(g + 8) * MSG_STRIDE + col] = s23;
        }
        if (w == 0) {
            int r0 = n0 + g, r1 = n0 + g + 8;
            if (tg < 2) {
                *(float2*)&g_as[r0 * NHEAD + tg * 2] = make_float2(cal[0], cal[1]);
                *(float2*)&g_as[r1 * NHEAD + tg * 2] = make_float2(cal[2], cal[3]);
                mx0 = fmaxf(mx0, fmaxf(cal[0], cal[2]));
                mx1 = fmaxf(mx1, fmaxf(cal[1], cal[3]));
            } else {
                int hh = (tg - 2) * 2;
                *(float2*)&g_ad[r0 * NHEAD + hh] = make_float2(cal[0], cal[1]);
                *(float2*)&g_ad[r1 * NHEAD + hh] = make_float2(cal[2], cal[3]);
            }
        }
        __syncthreads();
        {
            int row = t >> 4, chunk = t & 15;
            uint4 v = *(const uint4*)&sh_msg[row * MSG_STRIDE + chunk * 16];
            *(uint4*)&g_hw8[(size_t)(n0 + row) * HC + chunk * 16] = v;
        }
        __syncthreads();
    }

    if (w == 0) {
#pragma unroll
        for (int off = 4; off <= 16; off <<= 1) {
            mx0 = fmaxf(mx0, __shfl_xor_sync(0xffffffffu, mx0, off));
            mx1 = fmaxf(mx1, __shfl_xor_sync(0xffffffffu, mx1, off));
        }
        if (lane < 2) {
            atomicMax(&g_amax[layer][lane * 2],     enc_f(mx0));
            atomicMax(&g_amax[layer][lane * 2 + 1], enc_f(mx1));
        }
    }
}

// warp per node: 8-edge pipelined single-pass softmax+gather, fp16 accumulation.
// LAST: fused mean-pool (atomicAdd into g_pool) instead of feature store.
template <int LAST>
__global__ void k_attn_gather(const float* __restrict__ bg, int layer) {
    int wid = (blockIdx.x * blockDim.x + threadIdx.x) >> 5;
    int lane = threadIdx.x & 31;
    if (wid >= NN) return;
    int r0 = g_rowptr[wid], r1 = g_rowptr[wid + 1];
    int hsel = lane >> 3;
    float adh = g_ad[wid * NHEAD + hsel];
    float Mh  = dec_f(g_amax[layer][hsel]);
    float mb  = Mh + adh;
    float m   = fmaxf(mb, mb * NEG);         // valid upper bound (lrelu monotone)

    float ws = 0.f;
    __half2 zz = __floats2half2_rn(0.f, 0.f);
    __half2 acc2[4] = {zz, zz, zz, zz};
    const uint2* hw2 = (const uint2*)g_hw8;

#define CVT_H2(DST, SRC)                                                      \
    { __half2_raw rr_ = __nv_cvt_fp8x2_to_halfraw2(                           \
          (__nv_fp8x2_storage_t)(SRC), __NV_E4M3);                            \
      DST = *(__half2*)&rr_; }

#define COMP(AV, HV)                                                          \
    {                                                                         \
        float v_ = (AV) + adh; v_ = fmaxf(v_, v_ * NEG);                      \
        float w_ = __expf(v_ - m);                                            \
        ws += w_;                                                             \
        __half2 wh_ = __half2half2(__float2half_rn(w_));                      \
        __half2 h0_, h1_, h2_, h3_;                                           \
        CVT_H2(h0_, (HV).x & 0xffffu); CVT_H2(h1_, (HV).x >> 16);             \
        CVT_H2(h2_, (HV).y & 0xffffu); CVT_H2(h3_, (HV).y >> 16);             \
        acc2[0] = __hfma2(wh_, h0_, acc2[0]);                                 \
        acc2[1] = __hfma2(wh_, h1_, acc2[1]);                                 \
        acc2[2] = __hfma2(wh_, h2_, acc2[2]);                                 \
        acc2[3] = __hfma2(wh_, h3_, acc2[3]);                                 \
    }

    int p = r0;
    for (; p + 7 < r1; p += 8) {
        int   si[8];
        float av[8];
        uint2 mv[8];
#pragma unroll
        for (int q = 0; q < 8; q++) si[q] = g_csr_src[p + q];
#pragma unroll
        for (int q = 0; q < 8; q++) av[q] = g_as[si[q] * NHEAD + hsel];
#pragma unroll
        for (int q = 0; q < 8; q++) mv[q] = hw2[(size_t)si[q] * 32 + lane];
#pragma unroll
        for (int q = 0; q < 8; q++) COMP(av[q], mv[q]);
    }
    for (; p + 3 < r1; p += 4) {
        int s0 = g_csr_src[p],     s1 = g_csr_src[p + 1];
        int s2 = g_csr_src[p + 2], s3 = g_csr_src[p + 3];
        float a0 = g_as[s0 * NHEAD + hsel], a1 = g_as[s1 * NHEAD + hsel];
        float a2 = g_as[s2 * NHEAD + hsel], a3 = g_as[s3 * NHEAD + hsel];
        uint2 m0 = hw2[(size_t)s0 * 32 + lane], m1 = hw2[(size_t)s1 * 32 + lane];
        uint2 m2 = hw2[(size_t)s2 * 32 + lane], m3 = hw2[(size_t)s3 * 32 + lane];
        COMP(a0, m0); COMP(a1, m1); COMP(a2, m2); COMP(a3, m3);
    }
    for (; p < r1; p++) {
        int s0 = g_csr_src[p];
        float a0 = g_as[s0 * NHEAD + hsel];
        uint2 m0 = hw2[(size_t)s0 * 32 + lane];
        COMP(a0, m0);
    }
#undef COMP
#undef CVT_H2

    float wi = 1.f / (ws + 1e-16f);
    float out[8];
#pragma unroll
    for (int j = 0; j < 4; j++) {
        float2 f = __half22float2(acc2[j]);
        out[2 * j]     = f.x;
        out[2 * j + 1] = f.y;
    }
#pragma unroll
    for (int qd = 0; qd < 8; qd++) {
        float v = out[qd] * wi;
        v += __shfl_xor_sync(0xffffffffu, v, 8);
        v += __shfl_xor_sync(0xffffffffu, v, 16);
        out[qd] = v;
    }
    if (lane < 8) {
#pragma unroll
        for (int qd = 0; qd < 8; qd++) {
            float v = out[qd] * 0.25f + bg[lane * 8 + qd];
            out[qd] = (v > 0.f) ? v : 0.f;
        }
        if (LAST) {
            int gph = g_batch[wid];
#pragma unroll
            for (int qd = 0; qd < 8; qd++)
                atomicAdd(&g_pool[gph * HIDD + lane * 8 + qd], out[qd]);
            if (lane == 0) atomicAdd(&g_cnt[gph], 1.f);
        } else {
            __half2* hdst = (__half2*)(g_hf + (size_t)wid * HIDD + lane * 8);
            hdst[0] = __floats2half2_rn(out[0], out[1]);
            hdst[1] = __floats2half2_rn(out[2], out[3]);
            hdst[2] = __floats2half2_rn(out[4], out[5]);
            hdst[3] = __floats2half2_rn(out[6], out[7]);
        }
    }
}

__global__ void k_final(const float* __restrict__ Wout, const float* __restrict__ bout,
                        float* __restrict__ out) {
    int g = threadIdx.x;
    if (g >= GG) return;
    float cnt = fmaxf(g_cnt[g], 1.f);
    float s = 0.f;
#pragma unroll
    for (int c = 0; c < HIDD; c++) s += (g_pool[g * HIDD + c] / cnt) * Wout[c];
    out[g] = 1.f / (1.f + expf(-(s + bout[0])));
}

// ---------------- launch ----------------
extern "C" void kernel_launch(void* const* d_in, const int* in_sizes, int n_in,
                              void* d_out, int out_size) {
    int ix, iei, ib, iwin, ibin, iwout, ibout, iw[3], ias[3], iad[3], ibg[3];
    if (n_in >= 2 && in_sizes[1] == 2 * EE) {
        ix = 0; iei = 1; ib = 2; iwin = 3; ibin = 4; iwout = 5; ibout = 6;
        for (int l = 0; l < 3; l++) { iw[l] = 7 + 4 * l; ias[l] = 8 + 4 * l; iad[l] = 9 + 4 * l; ibg[l] = 10 + 4 * l; }
    } else {
        ix = 0; iwin = 1; ibin = 2;
        for (int l = 0; l < 3; l++) { iw[l] = 3 + 4 * l; ias[l] = 4 + 4 * l; iad[l] = 5 + 4 * l; ibg[l] = 6 + 4 * l; }
        iwout = 15; ibout = 16; iei = 17; ib = 18;
    }

    const float* x     = (const float*)d_in[ix];
    const void*  ei    = d_in[iei];
    const void*  batch = d_in[ib];
    const float* W_in  = (const float*)d_in[iwin];
    const float* b_in  = (const float*)d_in[ibin];
    const float* W_out = (const float*)d_in[iwout];
    const float* b_out = (const float*)d_in[ibout];
    float* out = (float*)d_out;

    // lazily-created side stream + events (first call = correctness run, uncaptured)
    static cudaStream_t s1 = nullptr;
    static cudaEvent_t eFork, eW0, eW1, eW2, eFill;
    if (!s1) {
        cudaStreamCreateWithFlags(&s1, cudaStreamNonBlocking);
        cudaEventCreateWithFlags(&eFork, cudaEventDisableTiming);
        cudaEventCreateWithFlags(&eW0,   cudaEventDisableTiming);
        cudaEventCreateWithFlags(&eW1,   cudaEventDisableTiming);
        cudaEventCreateWithFlags(&eW2,   cudaEventDisableTiming);
        cudaEventCreateWithFlags(&eFill, cudaEventDisableTiming);
    }

    const int T = 256;
    auto gsz = [](long long n, int t) { return (int)((n + t - 1) / t); };
    const int WPG = gsz(KP * HC + 256 + NHEAD, T);

    // fork side stream
    cudaEventRecord(eFork, 0);
    cudaStreamWaitEvent(s1, eFork, 0);

    // side stream: wpack0, CSR build, wpack1, wpack2
    k_wpack<<<WPG, T, 0, s1>>>((const float*)d_in[iw[0]], (const float*)d_in[ias[0]],
                               (const float*)d_in[iad[0]], 0);
    cudaEventRecord(eW0, s1);
    k_zero<<<gsz(NN, T), T, 0, s1>>>();
    k_deg<<<gsz(EE, T), T, 0, s1>>>(ei, batch);
    k_scan1<<<SCAN_NBLK, SCAN_B, 0, s1>>>();
    k_scanfix<<<gsz(NN, T), T, 0, s1>>>();
    k_wpack<<<WPG, T, 0, s1>>>((const float*)d_in[iw[1]], (const float*)d_in[ias[1]],
                               (const float*)d_in[iad[1]], 1);
    cudaEventRecord(eW1, s1);
    k_wpack<<<WPG, T, 0, s1>>>((const float*)d_in[iw[2]], (const float*)d_in[ias[2]],
                               (const float*)d_in[iad[2]], 2);
    cudaEventRecord(eW2, s1);
    k_fill<<<gsz(ELNUM, T), T, 0, s1>>>(ei);
    cudaEventRecord(eFill, s1);

    // main stream: node pipeline
    k_lin_in<<<gsz((long long)NN * HIDD, T), T>>>(x, W_in, b_in);
    cudaStreamWaitEvent(0, eW0, 0);
    k_mma<<<MMA_GRID, 256>>>(0);
    cudaStreamWaitEvent(0, eFill, 0);
    k_attn_gather<0><<<gsz((long long)NN * 32, T), T>>>((const float*)d_in[ibg[0]], 0);

    cudaStreamWaitEvent(0, eW1, 0);
    k_mma<<<MMA_GRID, 256>>>(1);
    k_attn_gather<0><<<gsz((long long)NN * 32, T), T>>>((const float*)d_in[ibg[1]], 1);

    cudaStreamWaitEvent(0, eW2, 0);
    k_mma<<<MMA_GRID, 256>>>(2);
    k_attn_gather<1><<<gsz((long long)NN * 32, T), T>>>((const float*)d_in[ibg[2]], 2);

    k_final<<<1, 64>>>(W_out, b_out, out);
}

// round 16
// speedup vs baseline: 1.7756x; 1.7756x over previous
#include <cuda_runtime.h>
#include <cuda_fp16.h>
#include <cuda_fp8.h>
#include <math.h>
#include <float.h>

#define NN    50000
#define EE    800000
#define ELNUM 850000          // EE + NN self loops
#define FIN   16
#define HIDD  64
#define NHEAD 4
#define CC    64
#define HC    256             // NHEAD*CC
#define GG    64
#define NEG   0.2f

#define SCAN_B    1024
#define SCAN_NBLK ((NN + SCAN_B - 1) / SCAN_B)   // 49

#define KP        (HIDD / 2)   // 32 k-pairs
#define MMA_GRID  296
#define NTILES    (NN / 16)    // 3125
#define MSG_STRIDE 272         // 16B-aligned, 4-bank row shift -> conflict-free

// ---------------- scratch (device globals; no allocation) ----------------
__device__ int      g_batch[NN];
__device__ int      g_deg[NN];
__device__ int      g_cursor[NN];
__device__ int      g_rowptr[NN + 1];
__device__ int      g_bsum[SCAN_NBLK];
__device__ int      g_csr_src[ELNUM];
__device__ unsigned g_amax[3][NHEAD];                      // encoded global max of as, per layer
__device__ __align__(16) float    g_h  [NN * HIDD];        // fp32 node features (final layer, for pool)
__device__ __align__(16) __half   g_hf [NN * HIDD];        // fp16 node features (GEMM A)
__device__ __align__(16) unsigned g_wtp[3 * KP * HC];      // per-layer W^T k-pair-packed half2
__device__ __align__(16) unsigned g_wap[3 * KP * 8];       // per-layer [Wᵀasrc|Wᵀadst] half2
__device__ __align__(16) unsigned char g_hw8[(size_t)NN * HC]; // h @ W^T as e4m3 [N, 256]
__device__ __align__(16) float    g_as [NN * NHEAD];       // a_src . h  per node
__device__ __align__(16) float    g_ad [NN * NHEAD];       // a_dst . h  per node
__device__ float g_pool[GG * HIDD];
__device__ float g_cnt [GG];

// monotone float<->uint encoding for atomicMax on signed floats
__device__ __forceinline__ unsigned enc_f(float f) {
    unsigned u = __float_as_uint(f);
    return (u & 0x80000000u) ? ~u : (u | 0x80000000u);
}
__device__ __forceinline__ float dec_f(unsigned k) {
    return (k & 0x80000000u) ? __uint_as_float(k & 0x7fffffffu)
                             : __uint_as_float(~k);
}

// shared-memory int64-vs-int32 consensus probe (first 64 values of ei row 0)
#define IS64_PROBE(EI_PTR, OUT)                                     \
    __shared__ int s_is64;                                          \
    if (threadIdx.x < 32) {                                         \
        const int* p_ = (const int*)(EI_PTR);                       \
        int bad_ = (p_[2 * threadIdx.x + 1] != 0);                  \
        unsigned b_ = __ballot_sync(0xffffffffu, bad_);             \
        if (threadIdx.x == 0) s_is64 = (b_ == 0u);                  \
    }                                                               \
    __syncthreads();                                                \
    int OUT = s_is64;

// ---------------- zero / degree / CSR ----------------
__global__ void k_zero() {
    int i = blockIdx.x * blockDim.x + threadIdx.x;
    if (i < NN) { g_deg[i] = 1; g_cursor[i] = 0; }   // deg=1: self loop
    if (i < GG * HIDD) g_pool[i] = 0.f;
    if (i < GG) g_cnt[i] = 0.f;
}

__global__ void k_deg(const void* ei, const void* batch) {
    IS64_PROBE(ei, is64);
    int i = blockIdx.x * blockDim.x + threadIdx.x;
    if (i < EE) {
        int d = is64 ? (int)((const long long*)ei)[EE + i]
                     : ((const int*)ei)[EE + i];
        atomicAdd(&g_deg[d], 1);
    }
    if (i < NN) {
        g_batch[i] = is64 ? (int)((const long long*)batch)[i]
                          : ((const int*)batch)[i];
    }
}

__global__ void k_scan1() {
    __shared__ int ws[32];
    int b = blockIdx.x, tid = threadIdx.x;
    int i = b * SCAN_B + tid;
    int lane = tid & 31, w = tid >> 5;
    int x = (i < NN) ? g_deg[i] : 0;
#pragma unroll
    for (int o = 1; o < 32; o <<= 1) {
        int y = __shfl_up_sync(0xffffffffu, x, o);
        if (lane >= o) x += y;
    }
    if (lane == 31) ws[w] = x;
    __syncthreads();
    if (w == 0) {
        int y = ws[lane];
#pragma unroll
        for (int o = 1; o < 32; o <<= 1) {
            int z = __shfl_up_sync(0xffffffffu, y, o);
            if (lane >= o) y += z;
        }
        ws[lane] = y;
    }
    __syncthreads();
    int incl = x + (w > 0 ? ws[w - 1] : 0);
    if (i < NN) g_rowptr[i + 1] = incl;
    if (tid == SCAN_B - 1) g_bsum[b] = incl;
}

__global__ void k_scanfix() {
    int i = blockIdx.x * blockDim.x + threadIdx.x;
    if (i >= NN) return;
    int b = i >> 10;
    int off = 0;
    for (int j = 0; j < b; j++) off += g_bsum[j];
    g_rowptr[i + 1] += off;
    if (i == 0) g_rowptr[0] = 0;
}

__global__ void k_fill(const void* ei) {
    IS64_PROBE(ei, is64);
    int i = blockIdx.x * blockDim.x + threadIdx.x;
    if (i >= ELNUM) return;
    int s, d;
    if (i < EE) {
        if (is64) {
            s = (int)((const long long*)ei)[i];
            d = (int)((const long long*)ei)[EE + i];
        } else {
            s = ((const int*)ei)[i];
            d = ((const int*)ei)[EE + i];
        }
    } else {
        s = d = i - EE;   // self loop
    }
    int pos = g_rowptr[d] + atomicAdd(&g_cursor[d], 1);
    g_csr_src[pos] = s;
}

// ---------------- compute kernels ----------------
__global__ void k_lin_in(const float* __restrict__ x, const float* __restrict__ W,
                         const float* __restrict__ b) {
    int i = blockIdx.x * blockDim.x + threadIdx.x;
    if (i >= NN * HIDD) return;
    int n = i / HIDD, c = i % HIDD;
    const float* xr = x + n * FIN;
    const float* wr = W + c * FIN;
    float s = b[c];
#pragma unroll
    for (int k = 0; k < FIN; k++) s += xr[k] * wr[k];
    g_hf[i] = __float2half(s);
}

// prepack W -> k-pair half2 (per-layer buffer) + alpha cols + zero amax[layer]
__global__ void k_wpack(const float* __restrict__ W,
                        const float* __restrict__ asrc,
                        const float* __restrict__ adst, int layer) {
    int i = blockIdx.x * blockDim.x + threadIdx.x;
    if (i < KP * HC) {
        int kp = i >> 8, n = i & 255;
        __half2 v = __floats2half2_rn(W[n * HIDD + 2 * kp], W[n * HIDD + 2 * kp + 1]);
        g_wtp[layer * KP * HC + i] = *(unsigned*)&v;
    } else if (i < KP * HC + 256) {
        int j = i - KP * HC;          // [0,256)
        int n8 = j >> 5, kp = j & 31; // n8: 0-3 as heads, 4-7 ad heads
        int h = n8 & 3;
        const float* a = (n8 >= 4) ? adst : asrc;
        float w0 = 0.f, w1 = 0.f;
#pragma unroll
        for (int c = 0; c < CC; c++) {
            float av = a[h * CC + c];
            const float* wr = W + (h * CC + c) * HIDD;
            w0 += av * wr[2 * kp];
            w1 += av * wr[2 * kp + 1];
        }
        __half2 v = __floats2half2_rn(w0, w1);
        g_wap[layer * KP * 8 + kp * 8 + n8] = *(unsigned*)&v;
    } else if (i < KP * HC + 256 + NHEAD) {
        g_amax[layer][i - (KP * HC + 256)] = 0u;   // < enc(-FLT_MAX)
    }
}

// Tensor-core GEMM + alpha columns + running global alpha-src max.
// A-tile staged in smem once per block (kills 8x redundant L1 traffic).
__global__ void __launch_bounds__(256) k_mma(int layer) {
    int t = threadIdx.x;
    int w = t >> 5, lane = t & 31;
    int g = lane >> 2, tg = lane & 3;
    const unsigned* wtp = g_wtp + layer * KP * HC;
    const unsigned* wap = g_wap + layer * KP * 8;

    unsigned bf[4][4][2];
#pragma unroll
    for (int kc = 0; kc < 4; kc++)
#pragma unroll
        for (int j = 0; j < 4; j++) {
            int n = w * 32 + j * 8 + g;
            bf[kc][j][0] = wtp[(kc * 8 + tg) * HC + n];
            bf[kc][j][1] = wtp[(kc * 8 + 4 + tg) * HC + n];
        }
    unsigned bfa[4][2];
#pragma unroll
    for (int kc = 0; kc < 4; kc++) {
        bfa[kc][0] = wap[(kc * 8 + tg) * 8 + g];
        bfa[kc][1] = wap[(kc * 8 + 4 + tg) * 8 + g];
    }

    float mx0 = -FLT_MAX, mx1 = -FLT_MAX;

    __shared__ __align__(16) unsigned char sh_msg[16 * MSG_STRIDE];
    __shared__ unsigned sh_a[16][36];   // stride 36 -> conflict-free fragment reads
    const unsigned* hfu = (const unsigned*)g_hf;

    for (int tile = blockIdx.x; tile < NTILES; tile += gridDim.x) {
        int n0 = tile * 16;

        // cooperative A-tile load: 16 rows x 32 uint (2KB), coalesced
#pragma unroll
        for (int idx = t; idx < 16 * 32; idx += 256) {
            int r = idx >> 5, c = idx & 31;
            sh_a[r][c] = hfu[(n0 + r) * 32 + c];
        }
        __syncthreads();

        unsigned af[4][4];
#pragma unroll
        for (int kc = 0; kc < 4; kc++) {
            int kb2 = kc * 8;
            af[kc][0] = sh_a[g][kb2 + tg];
            af[kc][1] = sh_a[g + 8][kb2 + tg];
            af[kc][2] = sh_a[g][kb2 + 4 + tg];
            af[kc][3] = sh_a[g + 8][kb2 + 4 + tg];
        }

        float c[4][4];
#pragma unroll
        for (int j = 0; j < 4; j++) { c[j][0] = c[j][1] = c[j][2] = c[j][3] = 0.f; }
#pragma unroll
        for (int kc = 0; kc < 4; kc++)
#pragma unroll
            for (int j = 0; j < 4; j++)
                asm volatile(
                    "mma.sync.aligned.m16n8k16.row.col.f32.f16.f16.f32 "
                    "{%0,%1,%2,%3}, {%4,%5,%6,%7}, {%8,%9}, {%0,%1,%2,%3};"
                    : "+f"(c[j][0]), "+f"(c[j][1]), "+f"(c[j][2]), "+f"(c[j][3])
                    : "r"(af[kc][0]), "r"(af[kc][1]), "r"(af[kc][2]), "r"(af[kc][3]),
                      "r"(bf[kc][j][0]), "r"(bf[kc][j][1]));

        float cal[4] = {0.f, 0.f, 0.f, 0.f};
        if (w == 0) {
#pragma unroll
            for (int kc = 0; kc < 4; kc++)
                asm volatile(
                    "mma.sync.aligned.m16n8k16.row.col.f32.f16.f16.f32 "
                    "{%0,%1,%2,%3}, {%4,%5,%6,%7}, {%8,%9}, {%0,%1,%2,%3};"
                    : "+f"(cal[0]), "+f"(cal[1]), "+f"(cal[2]), "+f"(cal[3])
                    : "r"(af[kc][0]), "r"(af[kc][1]), "r"(af[kc][2]), "r"(af[kc][3]),
                      "r"(bfa[kc][0]), "r"(bfa[kc][1]));
        }

#pragma unroll
        for (int j = 0; j < 4; j++) {
            int col = w * 32 + j * 8 + tg * 2;
            __nv_fp8x2_storage_t s01 = __nv_cvt_float2_to_fp8x2(
                make_float2(c[j][0], c[j][1]), __NV_SATFINITE, __NV_E4M3);
            __nv_fp8x2_storage_t s23 = __nv_cvt_float2_to_fp8x2(
                make_float2(c[j][2], c[j][3]), __NV_SATFINITE, __NV_E4M3);
            *(unsigned short*)&sh_msg[g * MSG_STRIDE + col]       = s01;
            *(unsigned short*)&sh_msg[(g + 8) * MSG_STRIDE + col] = s23;
        }
        if (w == 0) {
            int r0 = n0 + g, r1 = n0 + g + 8;
            if (tg < 2) {
                *(float2*)&g_as[r0 * NHEAD + tg * 2] = make_float2(cal[0], cal[1]);
                *(float2*)&g_as[r1 * NHEAD + tg * 2] = make_float2(cal[2], cal[3]);
                mx0 = fmaxf(mx0, fmaxf(cal[0], cal[2]));
                mx1 = fmaxf(mx1, fmaxf(cal[1], cal[3]));
            } else {
                int hh = (tg - 2) * 2;
                *(float2*)&g_ad[r0 * NHEAD + hh] = make_float2(cal[0], cal[1]);
                *(float2*)&g_ad[r1 * NHEAD + hh] = make_float2(cal[2], cal[3]);
            }
        }
        __syncthreads();
        {
            int row = t >> 4, chunk = t & 15;
            uint4 v = *(const uint4*)&sh_msg[row * MSG_STRIDE + chunk * 16];
            *(uint4*)&g_hw8[(size_t)(n0 + row) * HC + chunk * 16] = v;
        }
        __syncthreads();
    }

    if (w == 0) {
#pragma unroll
        for (int off = 4; off <= 16; off <<= 1) {
            mx0 = fmaxf(mx0, __shfl_xor_sync(0xffffffffu, mx0, off));
            mx1 = fmaxf(mx1, __shfl_xor_sync(0xffffffffu, mx1, off));
        }
        if (lane < 2) {
            atomicMax(&g_amax[layer][lane * 2],     enc_f(mx0));
            atomicMax(&g_amax[layer][lane * 2 + 1], enc_f(mx1));
        }
    }
}

// warp per node: 8-edge pipelined single-pass softmax+gather, fp16 accumulation.
// LAST!=0 -> fp32 g_h store (for pool); else fp16 g_hf.
template <int LAST>
__global__ void k_attn_gather(const float* __restrict__ bg, int layer) {
    int wid = (blockIdx.x * blockDim.x + threadIdx.x) >> 5;
    int lane = threadIdx.x & 31;
    if (wid >= NN) return;
    int r0 = g_rowptr[wid], r1 = g_rowptr[wid + 1];
    int hsel = lane >> 3;
    float adh = g_ad[wid * NHEAD + hsel];
    float Mh  = dec_f(g_amax[layer][hsel]);
    float mb  = Mh + adh;
    float m   = fmaxf(mb, mb * NEG);         // valid upper bound (lrelu monotone)

    float ws = 0.f;
    __half2 zz = __floats2half2_rn(0.f, 0.f);
    __half2 acc2[4] = {zz, zz, zz, zz};
    const uint2* hw2 = (const uint2*)g_hw8;

#define CVT_H2(DST, SRC)                                                      \
    { __half2_raw rr_ = __nv_cvt_fp8x2_to_halfraw2(                           \
          (__nv_fp8x2_storage_t)(SRC), __NV_E4M3);                            \
      DST = *(__half2*)&rr_; }

#define COMP(AV, HV)                                                          \
    {                                                                         \
        float v_ = (AV) + adh; v_ = fmaxf(v_, v_ * NEG);                      \
        float w_ = __expf(v_ - m);                                            \
        ws += w_;                                                             \
        __half2 wh_ = __half2half2(__float2half_rn(w_));                      \
        __half2 h0_, h1_, h2_, h3_;                                           \
        CVT_H2(h0_, (HV).x & 0xffffu); CVT_H2(h1_, (HV).x >> 16);             \
        CVT_H2(h2_, (HV).y & 0xffffu); CVT_H2(h3_, (HV).y >> 16);             \
        acc2[0] = __hfma2(wh_, h0_, acc2[0]);                                 \
        acc2[1] = __hfma2(wh_, h1_, acc2[1]);                                 \
        acc2[2] = __hfma2(wh_, h2_, acc2[2]);                                 \
        acc2[3] = __hfma2(wh_, h3_, acc2[3]);                                 \
    }

    int p = r0;
    for (; p + 7 < r1; p += 8) {
        int   si[8];
        float av[8];
        uint2 mv[8];
#pragma unroll
        for (int q = 0; q < 8; q++) si[q] = g_csr_src[p + q];
#pragma unroll
        for (int q = 0; q < 8; q++) av[q] = g_as[si[q] * NHEAD + hsel];
#pragma unroll
        for (int q = 0; q < 8; q++) mv[q] = hw2[(size_t)si[q] * 32 + lane];
#pragma unroll
        for (int q = 0; q < 8; q++) COMP(av[q], mv[q]);
    }
    for (; p + 3 < r1; p += 4) {
        int s0 = g_csr_src[p],     s1 = g_csr_src[p + 1];
        int s2 = g_csr_src[p + 2], s3 = g_csr_src[p + 3];
        float a0 = g_as[s0 * NHEAD + hsel], a1 = g_as[s1 * NHEAD + hsel];
        float a2 = g_as[s2 * NHEAD + hsel], a3 = g_as[s3 * NHEAD + hsel];
        uint2 m0 = hw2[(size_t)s0 * 32 + lane], m1 = hw2[(size_t)s1 * 32 + lane];
        uint2 m2 = hw2[(size_t)s2 * 32 + lane], m3 = hw2[(size_t)s3 * 32 + lane];
        COMP(a0, m0); COMP(a1, m1); COMP(a2, m2); COMP(a3, m3);
    }
    for (; p < r1; p++) {
        int s0 = g_csr_src[p];
        float a0 = g_as[s0 * NHEAD + hsel];
        uint2 m0 = hw2[(size_t)s0 * 32 + lane];
        COMP(a0, m0);
    }
#undef COMP
#undef CVT_H2

    float wi = 1.f / (ws + 1e-16f);
    float out[8];
#pragma unroll
    for (int j = 0; j < 4; j++) {
        float2 f = __half22float2(acc2[j]);
        out[2 * j]     = f.x;
        out[2 * j + 1] = f.y;
    }
#pragma unroll
    for (int qd = 0; qd < 8; qd++) {
        float v = out[qd] * wi;
        v += __shfl_xor_sync(0xffffffffu, v, 8);
        v += __shfl_xor_sync(0xffffffffu, v, 16);
        out[qd] = v;
    }
    if (lane < 8) {
#pragma unroll
        for (int qd = 0; qd < 8; qd++) {
            float v = out[qd] * 0.25f + bg[lane * 8 + qd];
            out[qd] = (v > 0.f) ? v : 0.f;
        }
        if (LAST) {
            float4* dst4 = (float4*)(g_h + (size_t)wid * HIDD + lane * 8);
            dst4[0] = make_float4(out[0], out[1], out[2], out[3]);
            dst4[1] = make_float4(out[4], out[5], out[6], out[7]);
        } else {
            __half2* hdst = (__half2*)(g_hf + (size_t)wid * HIDD + lane * 8);
            hdst[0] = __floats2half2_rn(out[0], out[1]);
            hdst[1] = __floats2half2_rn(out[2], out[3]);
            hdst[2] = __floats2half2_rn(out[4], out[5]);
            hdst[3] = __floats2half2_rn(out[6], out[7]);
        }
    }
}

// thread handles channel c over 16 consecutive (batch-sorted) nodes; run-length merge
__global__ void k_pool() {
    int i = blockIdx.x * blockDim.x + threadIdx.x;
    int c = i & 63;
    int n0 = (i >> 6) * 16;
    if (n0 >= NN) return;
    float run = 0.f; float cnt = 0.f; int gcur = -1;
#pragma unroll
    for (int t = 0; t < 16; t++) {
        int n = n0 + t;
        if (n >= NN) break;
        int g = g_batch[n];
        if (g != gcur) {
            if (gcur >= 0) {
                atomicAdd(&g_pool[gcur * HIDD + c], run);
                if (c == 0) atomicAdd(&g_cnt[gcur], cnt);
            }
            gcur = g; run = 0.f; cnt = 0.f;
        }
        run += g_h[n * HIDD + c];
        cnt += 1.f;
    }
    if (gcur >= 0) {
        atomicAdd(&g_pool[gcur * HIDD + c], run);
        if (c == 0) atomicAdd(&g_cnt[gcur], cnt);
    }
}

__global__ void k_final(const float* __restrict__ Wout, const float* __restrict__ bout,
                        float* __restrict__ out) {
    int g = threadIdx.x;
    if (g >= GG) return;
    float cnt = fmaxf(g_cnt[g], 1.f);
    float s = 0.f;
#pragma unroll
    for (int c = 0; c < HIDD; c++) s += (g_pool[g * HIDD + c] / cnt) * Wout[c];
    out[g] = 1.f / (1.f + expf(-(s + bout[0])));
}

// ---------------- launch ----------------
extern "C" void kernel_launch(void* const* d_in, const int* in_sizes, int n_in,
                              void* d_out, int out_size) {
    int ix, iei, ib, iwin, ibin, iwout, ibout, iw[3], ias[3], iad[3], ibg[3];
    if (n_in >= 2 && in_sizes[1] == 2 * EE) {
        ix = 0; iei = 1; ib = 2; iwin = 3; ibin = 4; iwout = 5; ibout = 6;
        for (int l = 0; l < 3; l++) { iw[l] = 7 + 4 * l; ias[l] = 8 + 4 * l; iad[l] = 9 + 4 * l; ibg[l] = 10 + 4 * l; }
    } else {
        ix = 0; iwin = 1; ibin = 2;
        for (int l = 0; l < 3; l++) { iw[l] = 3 + 4 * l; ias[l] = 4 + 4 * l; iad[l] = 5 + 4 * l; ibg[l] = 6 + 4 * l; }
        iwout = 15; ibout = 16; iei = 17; ib = 18;
    }

    const float* x     = (const float*)d_in[ix];
    const void*  ei    = d_in[iei];
    const void*  batch = d_in[ib];
    const float* W_in  = (const float*)d_in[iwin];
    const float* b_in  = (const float*)d_in[ibin];
    const float* W_out = (const float*)d_in[iwout];
    const float* b_out = (const float*)d_in[ibout];
    float* out = (float*)d_out;

    // lazily-created side stream + events (first call = correctness run, uncaptured)
    static cudaStream_t s1 = nullptr;
    static cudaEvent_t eFork, eW0, eW1, eW2, eFill;
    if (!s1) {
        cudaStreamCreateWithFlags(&s1, cudaStreamNonBlocking);
        cudaEventCreateWithFlags(&eFork, cudaEventDisableTiming);
        cudaEventCreateWithFlags(&eW0,   cudaEventDisableTiming);
        cudaEventCreateWithFlags(&eW1,   cudaEventDisableTiming);
        cudaEventCreateWithFlags(&eW2,   cudaEventDisableTiming);
        cudaEventCreateWithFlags(&eFill, cudaEventDisableTiming);
    }

    const int T = 256;
    auto gsz = [](long long n, int t) { return (int)((n + t - 1) / t); };
    const int WPG = gsz(KP * HC + 256 + NHEAD, T);

    // fork side stream
    cudaEventRecord(eFork, 0);
    cudaStreamWaitEvent(s1, eFork, 0);

    // side stream: wpack0, CSR build, wpack1, wpack2
    k_wpack<<<WPG, T, 0, s1>>>((const float*)d_in[iw[0]], (const float*)d_in[ias[0]],
                               (const float*)d_in[iad[0]], 0);
    cudaEventRecord(eW0, s1);
    k_zero<<<gsz(NN, T), T, 0, s1>>>();
    k_deg<<<gsz(EE, T), T, 0, s1>>>(ei, batch);
    k_scan1<<<SCAN_NBLK, SCAN_B, 0, s1>>>();
    k_scanfix<<<gsz(NN, T), T, 0, s1>>>();
    k_wpack<<<WPG, T, 0, s1>>>((const float*)d_in[iw[1]], (const float*)d_in[ias[1]],
                               (const float*)d_in[iad[1]], 1);
    cudaEventRecord(eW1, s1);
    k_wpack<<<WPG, T, 0, s1>>>((const float*)d_in[iw[2]], (const float*)d_in[ias[2]],
                               (const float*)d_in[iad[2]], 2);
    cudaEventRecord(eW2, s1);
    k_fill<<<gsz(ELNUM, T), T, 0, s1>>>(ei);
    cudaEventRecord(eFill, s1);

    // main stream: node pipeline
    k_lin_in<<<gsz((long long)NN * HIDD, T), T>>>(x, W_in, b_in);
    cudaStreamWaitEvent(0, eW0, 0);
    k_mma<<<MMA_GRID, 256>>>(0);
    cudaStreamWaitEvent(0, eFill, 0);
    k_attn_gather<0><<<gsz((long long)NN * 32, T), T>>>((const float*)d_in[ibg[0]], 0);

    cudaStreamWaitEvent(0, eW1, 0);
    k_mma<<<MMA_GRID, 256>>>(1);
    k_attn_gather<0><<<gsz((long long)NN * 32, T), T>>>((const float*)d_in[ibg[1]], 1);

    cudaStreamWaitEvent(0, eW2, 0);
    k_mma<<<MMA_GRID, 256>>>(2);
    k_attn_gather<1><<<gsz((long long)NN * 32, T), T>>>((const float*)d_in[ibg[2]], 2);

    k_pool<<<gsz((long long)((NN + 15) / 16) * HIDD, T), T>>>();
    k_final<<<1, 64>>>(W_out, b_out, out);
}

// round 17
// speedup vs baseline: 1.8729x; 1.0548x over previous
#include <cuda_runtime.h>
#include <cuda_fp16.h>
#include <cuda_fp8.h>
#include <math.h>
#include <float.h>

#define NN    50000
#define EE    800000
#define ELNUM 850000          // EE + NN self loops
#define FIN   16
#define HIDD  64
#define NHEAD 4
#define CC    64
#define HC    256             // NHEAD*CC
#define GG    64
#define NEG   0.2f

#define SCAN_B    1024
#define SCAN_NBLK ((NN + SCAN_B - 1) / SCAN_B)   // 49

#define KP        (HIDD / 2)   // 32 k-pairs
#define MMA_GRID  296
#define NTILES    (NN / 16)    // 3125
#define MSG_STRIDE 272         // 16B-aligned, 4-bank row shift -> conflict-free

// ---------------- scratch (device globals; no allocation) ----------------
__device__ int      g_batch[NN];
__device__ int      g_deg[NN];
__device__ int      g_cursor[NN];
__device__ int      g_rowptr[NN + 1];
__device__ int      g_bsum[SCAN_NBLK];
__device__ int      g_csr_src[ELNUM];
__device__ unsigned g_amax[3][NHEAD];                      // encoded global max of as, per layer
__device__ __align__(16) float    g_h  [NN * HIDD];        // fp32 node features (final layer, for pool)
__device__ __align__(16) __half   g_hf [NN * HIDD];        // fp16 node features (GEMM A)
__device__ __align__(16) unsigned g_wtp[3 * KP * HC];      // per-layer W^T k-pair-packed half2
__device__ __align__(16) unsigned g_wap[3 * KP * 8];       // per-layer [Wᵀasrc|Wᵀadst] half2
__device__ __align__(16) unsigned char g_hw8[(size_t)NN * HC]; // h @ W^T as e4m3 [N, 256]
__device__ __align__(16) float    g_as [NN * NHEAD];       // a_src . h  per node
__device__ __align__(16) float    g_ad [NN * NHEAD];       // a_dst . h  per node
__device__ float g_pool[GG * HIDD];
__device__ float g_cnt [GG];

// monotone float<->uint encoding for atomicMax on signed floats
__device__ __forceinline__ unsigned enc_f(float f) {
    unsigned u = __float_as_uint(f);
    return (u & 0x80000000u) ? ~u : (u | 0x80000000u);
}
__device__ __forceinline__ float dec_f(unsigned k) {
    return (k & 0x80000000u) ? __uint_as_float(k & 0x7fffffffu)
                             : __uint_as_float(~k);
}

// shared-memory int64-vs-int32 consensus probe (first 64 values of ei row 0)
#define IS64_PROBE(EI_PTR, OUT)                                     \
    __shared__ int s_is64;                                          \
    if (threadIdx.x < 32) {                                         \
        const int* p_ = (const int*)(EI_PTR);                       \
        int bad_ = (p_[2 * threadIdx.x + 1] != 0);                  \
        unsigned b_ = __ballot_sync(0xffffffffu, bad_);             \
        if (threadIdx.x == 0) s_is64 = (b_ == 0u);                  \
    }                                                               \
    __syncthreads();                                                \
    int OUT = s_is64;

// ---------------- zero / degree / CSR ----------------
__global__ void k_zero() {
    int i = blockIdx.x * blockDim.x + threadIdx.x;
    if (i < NN) { g_deg[i] = 1; g_cursor[i] = 0; }   // deg=1: self loop
    if (i < GG * HIDD) g_pool[i] = 0.f;
    if (i < GG) g_cnt[i] = 0.f;
}

__global__ void k_deg(const void* ei, const void* batch) {
    IS64_PROBE(ei, is64);
    int i = blockIdx.x * blockDim.x + threadIdx.x;
    if (i < EE) {
        int d = is64 ? (int)((const long long*)ei)[EE + i]
                     : ((const int*)ei)[EE + i];
        atomicAdd(&g_deg[d], 1);
    }
    if (i < NN) {
        g_batch[i] = is64 ? (int)((const long long*)batch)[i]
                          : ((const int*)batch)[i];
    }
}

__global__ void k_scan1() {
    __shared__ int ws[32];
    int b = blockIdx.x, tid = threadIdx.x;
    int i = b * SCAN_B + tid;
    int lane = tid & 31, w = tid >> 5;
    int x = (i < NN) ? g_deg[i] : 0;
#pragma unroll
    for (int o = 1; o < 32; o <<= 1) {
        int y = __shfl_up_sync(0xffffffffu, x, o);
        if (lane >= o) x += y;
    }
    if (lane == 31) ws[w] = x;
    __syncthreads();
    if (w == 0) {
        int y = ws[lane];
#pragma unroll
        for (int o = 1; o < 32; o <<= 1) {
            int z = __shfl_up_sync(0xffffffffu, y, o);
            if (lane >= o) y += z;
        }
        ws[lane] = y;
    }
    __syncthreads();
    int incl = x + (w > 0 ? ws[w - 1] : 0);
    if (i < NN) g_rowptr[i + 1] = incl;
    if (tid == SCAN_B - 1) g_bsum[b] = incl;
}

__global__ void k_scanfix() {
    int i = blockIdx.x * blockDim.x + threadIdx.x;
    if (i >= NN) return;
    int b = i >> 10;
    int off = 0;
    for (int j = 0; j < b; j++) off += g_bsum[j];
    g_rowptr[i + 1] += off;
    if (i == 0) g_rowptr[0] = 0;
}

__global__ void k_fill(const void* ei) {
    IS64_PROBE(ei, is64);
    int i = blockIdx.x * blockDim.x + threadIdx.x;
    if (i >= ELNUM) return;
    int s, d;
    if (i < EE) {
        if (is64) {
            s = (int)((const long long*)ei)[i];
            d = (int)((const long long*)ei)[EE + i];
        } else {
            s = ((const int*)ei)[i];
            d = ((const int*)ei)[EE + i];
        }
    } else {
        s = d = i - EE;   // self loop
    }
    int pos = g_rowptr[d] + atomicAdd(&g_cursor[d], 1);
    g_csr_src[pos] = s;
}

// ---------------- compute kernels ----------------
__global__ void k_lin_in(const float* __restrict__ x, const float* __restrict__ W,
                         const float* __restrict__ b) {
    int i = blockIdx.x * blockDim.x + threadIdx.x;
    if (i >= NN * HIDD) return;
    int n = i / HIDD, c = i % HIDD;
    const float* xr = x + n * FIN;
    const float* wr = W + c * FIN;
    float s = b[c];
#pragma unroll
    for (int k = 0; k < FIN; k++) s += xr[k] * wr[k];
    g_hf[i] = __float2half(s);
}

// prepack W -> k-pair half2 (per-layer buffer) + alpha cols + zero amax[layer]
__global__ void k_wpack(const float* __restrict__ W,
                        const float* __restrict__ asrc,
                        const float* __restrict__ adst, int layer) {
    int i = blockIdx.x * blockDim.x + threadIdx.x;
    if (i < KP * HC) {
        int kp = i >> 8, n = i & 255;
        __half2 v = __floats2half2_rn(W[n * HIDD + 2 * kp], W[n * HIDD + 2 * kp + 1]);
        g_wtp[layer * KP * HC + i] = *(unsigned*)&v;
    } else if (i < KP * HC + 256) {
        int j = i - KP * HC;          // [0,256)
        int n8 = j >> 5, kp = j & 31; // n8: 0-3 as heads, 4-7 ad heads
        int h = n8 & 3;
        const float* a = (n8 >= 4) ? adst : asrc;
        float w0 = 0.f, w1 = 0.f;
#pragma unroll
        for (int c = 0; c < CC; c++) {
            float av = a[h * CC + c];
            const float* wr = W + (h * CC + c) * HIDD;
            w0 += av * wr[2 * kp];
            w1 += av * wr[2 * kp + 1];
        }
        __half2 v = __floats2half2_rn(w0, w1);
        g_wap[layer * KP * 8 + kp * 8 + n8] = *(unsigned*)&v;
    } else if (i < KP * HC + 256 + NHEAD) {
        g_amax[layer][i - (KP * HC + 256)] = 0u;   // < enc(-FLT_MAX)
    }
}

// Tensor-core GEMM + alpha columns + running global alpha-src max.
// A-tile staged in smem once per block (kills 8x redundant L1 traffic).
__global__ void __launch_bounds__(256) k_mma(int layer) {
    int t = threadIdx.x;
    int w = t >> 5, lane = t & 31;
    int g = lane >> 2, tg = lane & 3;
    const unsigned* wtp = g_wtp + layer * KP * HC;
    const unsigned* wap = g_wap + layer * KP * 8;

    unsigned bf[4][4][2];
#pragma unroll
    for (int kc = 0; kc < 4; kc++)
#pragma unroll
        for (int j = 0; j < 4; j++) {
            int n = w * 32 + j * 8 + g;
            bf[kc][j][0] = wtp[(kc * 8 + tg) * HC + n];
            bf[kc][j][1] = wtp[(kc * 8 + 4 + tg) * HC + n];
        }
    unsigned bfa[4][2];
#pragma unroll
    for (int kc = 0; kc < 4; kc++) {
        bfa[kc][0] = wap[(kc * 8 + tg) * 8 + g];
        bfa[kc][1] = wap[(kc * 8 + 4 + tg) * 8 + g];
    }

    float mx0 = -FLT_MAX, mx1 = -FLT_MAX;

    __shared__ __align__(16) unsigned char sh_msg[16 * MSG_STRIDE];
    __shared__ unsigned sh_a[16][36];   // stride 36 -> conflict-free fragment reads
    const unsigned* hfu = (const unsigned*)g_hf;

    for (int tile = blockIdx.x; tile < NTILES; tile += gridDim.x) {
        int n0 = tile * 16;

        // cooperative A-tile load: 16 rows x 32 uint (2KB), coalesced
#pragma unroll
        for (int idx = t; idx < 16 * 32; idx += 256) {
            int r = idx >> 5, c = idx & 31;
            sh_a[r][c] = hfu[(n0 + r) * 32 + c];
        }
        __syncthreads();

        unsigned af[4][4];
#pragma unroll
        for (int kc = 0; kc < 4; kc++) {
            int kb2 = kc * 8;
            af[kc][0] = sh_a[g][kb2 + tg];
            af[kc][1] = sh_a[g + 8][kb2 + tg];
            af[kc][2] = sh_a[g][kb2 + 4 + tg];
            af[kc][3] = sh_a[g + 8][kb2 + 4 + tg];
        }

        float c[4][4];
#pragma unroll
        for (int j = 0; j < 4; j++) { c[j][0] = c[j][1] = c[j][2] = c[j][3] = 0.f; }
#pragma unroll
        for (int kc = 0; kc < 4; kc++)
#pragma unroll
            for (int j = 0; j < 4; j++)
                asm volatile(
                    "mma.sync.aligned.m16n8k16.row.col.f32.f16.f16.f32 "
                    "{%0,%1,%2,%3}, {%4,%5,%6,%7}, {%8,%9}, {%0,%1,%2,%3};"
                    : "+f"(c[j][0]), "+f"(c[j][1]), "+f"(c[j][2]), "+f"(c[j][3])
                    : "r"(af[kc][0]), "r"(af[kc][1]), "r"(af[kc][2]), "r"(af[kc][3]),
                      "r"(bf[kc][j][0]), "r"(bf[kc][j][1]));

        float cal[4] = {0.f, 0.f, 0.f, 0.f};
        if (w == 0) {
#pragma unroll
            for (int kc = 0; kc < 4; kc++)
                asm volatile(
                    "mma.sync.aligned.m16n8k16.row.col.f32.f16.f16.f32 "
                    "{%0,%1,%2,%3}, {%4,%5,%6,%7}, {%8,%9}, {%0,%1,%2,%3};"
                    : "+f"(cal[0]), "+f"(cal[1]), "+f"(cal[2]), "+f"(cal[3])
                    : "r"(af[kc][0]), "r"(af[kc][1]), "r"(af[kc][2]), "r"(af[kc][3]),
                      "r"(bfa[kc][0]), "r"(bfa[kc][1]));
        }

#pragma unroll
        for (int j = 0; j < 4; j++) {
            int col = w * 32 + j * 8 + tg * 2;
            __nv_fp8x2_storage_t s01 = __nv_cvt_float2_to_fp8x2(
                make_float2(c[j][0], c[j][1]), __NV_SATFINITE, __NV_E4M3);
            __nv_fp8x2_storage_t s23 = __nv_cvt_float2_to_fp8x2(
                make_float2(c[j][2], c[j][3]), __NV_SATFINITE, __NV_E4M3);
            *(unsigned short*)&sh_msg[g * MSG_STRIDE + col]       = s01;
            *(unsigned short*)&sh_msg[(g + 8) * MSG_STRIDE + col] = s23;
        }
        if (w == 0) {
            int r0 = n0 + g, r1 = n0 + g + 8;
            if (tg < 2) {
                *(float2*)&g_as[r0 * NHEAD + tg * 2] = make_float2(cal[0], cal[1]);
                *(float2*)&g_as[r1 * NHEAD + tg * 2] = make_float2(cal[2], cal[3]);
                mx0 = fmaxf(mx0, fmaxf(cal[0], cal[2]));
                mx1 = fmaxf(mx1, fmaxf(cal[1], cal[3]));
            } else {
                int hh = (tg - 2) * 2;
                *(float2*)&g_ad[r0 * NHEAD + hh] = make_float2(cal[0], cal[1]);
                *(float2*)&g_ad[r1 * NHEAD + hh] = make_float2(cal[2], cal[3]);
            }
        }
        __syncthreads();
        {
            int row = t >> 4, chunk = t & 15;
            uint4 v = *(const uint4*)&sh_msg[row * MSG_STRIDE + chunk * 16];
            *(uint4*)&g_hw8[(size_t)(n0 + row) * HC + chunk * 16] = v;
        }
        __syncthreads();
    }

    if (w == 0) {
#pragma unroll
        for (int off = 4; off <= 16; off <<= 1) {
            mx0 = fmaxf(mx0, __shfl_xor_sync(0xffffffffu, mx0, off));
            mx1 = fmaxf(mx1, __shfl_xor_sync(0xffffffffu, mx1, off));
        }
        if (lane < 2) {
            atomicMax(&g_amax[layer][lane * 2],     enc_f(mx0));
            atomicMax(&g_amax[layer][lane * 2 + 1], enc_f(mx1));
        }
    }
}

// warp per node: 8-edge pipelined single-pass softmax+gather, fp16 accumulation.
// LAST!=0 -> fp32 g_h store (for pool); else fp16 g_hf.
template <int LAST>
__global__ void k_attn_gather(const float* __restrict__ bg, int layer) {
    int wid = (blockIdx.x * blockDim.x + threadIdx.x) >> 5;
    int lane = threadIdx.x & 31;
    if (wid >= NN) return;
    int r0 = g_rowptr[wid], r1 = g_rowptr[wid + 1];
    int hsel = lane >> 3;
    float adh = g_ad[wid * NHEAD + hsel];
    float Mh  = dec_f(g_amax[layer][hsel]);
    float mb  = Mh + adh;
    float m   = fmaxf(mb, mb * NEG);         // valid upper bound (lrelu monotone)

    float ws = 0.f;
    __half2 zz = __floats2half2_rn(0.f, 0.f);
    __half2 acc2[4] = {zz, zz, zz, zz};
    const uint2* hw2 = (const uint2*)g_hw8;

#define CVT_H2(DST, SRC)                                                      \
    { __half2_raw rr_ = __nv_cvt_fp8x2_to_halfraw2(                           \
          (__nv_fp8x2_storage_t)(SRC), __NV_E4M3);                            \
      DST = *(__half2*)&rr_; }

#define COMP(AV, HV)                                                          \
    {                                                                         \
        float v_ = (AV) + adh; v_ = fmaxf(v_, v_ * NEG);                      \
        float w_ = __expf(v_ - m);                                            \
        ws += w_;                                                             \
        __half2 wh_ = __half2half2(__float2half_rn(w_));                      \
        __half2 h0_, h1_, h2_, h3_;                                           \
        CVT_H2(h0_, (HV).x & 0xffffu); CVT_H2(h1_, (HV).x >> 16);             \
        CVT_H2(h2_, (HV).y & 0xffffu); CVT_H2(h3_, (HV).y >> 16);             \
        acc2[0] = __hfma2(wh_, h0_, acc2[0]);                                 \
        acc2[1] = __hfma2(wh_, h1_, acc2[1]);                                 \
        acc2[2] = __hfma2(wh_, h2_, acc2[2]);                                 \
        acc2[3] = __hfma2(wh_, h3_, acc2[3]);                                 \
    }

    int p = r0;
    for (; p + 7 < r1; p += 8) {
        int   si[8];
        float av[8];
        uint2 mv[8];
#pragma unroll
        for (int q = 0; q < 8; q++) si[q] = g_csr_src[p + q];
#pragma unroll
        for (int q = 0; q < 8; q++) av[q] = g_as[si[q] * NHEAD + hsel];
#pragma unroll
        for (int q = 0; q < 8; q++) mv[q] = hw2[(size_t)si[q] * 32 + lane];
#pragma unroll
        for (int q = 0; q < 8; q++) COMP(av[q], mv[q]);
    }
    for (; p + 3 < r1; p += 4) {
        int s0 = g_csr_src[p],     s1 = g_csr_src[p + 1];
        int s2 = g_csr_src[p + 2], s3 = g_csr_src[p + 3];
        float a0 = g_as[s0 * NHEAD + hsel], a1 = g_as[s1 * NHEAD + hsel];
        float a2 = g_as[s2 * NHEAD + hsel], a3 = g_as[s3 * NHEAD + hsel];
        uint2 m0 = hw2[(size_t)s0 * 32 + lane], m1 = hw2[(size_t)s1 * 32 + lane];
        uint2 m2 = hw2[(size_t)s2 * 32 + lane], m3 = hw2[(size_t)s3 * 32 + lane];
        COMP(a0, m0); COMP(a1, m1); COMP(a2, m2); COMP(a3, m3);
    }
    for (; p < r1; p++) {
        int s0 = g_csr_src[p];
        float a0 = g_as[s0 * NHEAD + hsel];
        uint2 m0 = hw2[(size_t)s0 * 32 + lane];
        COMP(a0, m0);
    }
#undef COMP
#undef CVT_H2

    float wi = 1.f / (ws + 1e-16f);
    float out[8];
#pragma unroll
    for (int j = 0; j < 4; j++) {
        float2 f = __half22float2(acc2[j]);
        out[2 * j]     = f.x;
        out[2 * j + 1] = f.y;
    }
#pragma unroll
    for (int qd = 0; qd < 8; qd++) {
        float v = out[qd] * wi;
        v += __shfl_xor_sync(0xffffffffu, v, 8);
        v += __shfl_xor_sync(0xffffffffu, v, 16);
        out[qd] = v;
    }
    if (lane < 8) {
#pragma unroll
        for (int qd = 0; qd < 8; qd++) {
            float v = out[qd] * 0.25f + bg[lane * 8 + qd];
            out[qd] = (v > 0.f) ? v : 0.f;
        }
        if (LAST) {
            float4* dst4 = (float4*)(g_h + (size_t)wid * HIDD + lane * 8);
            dst4[0] = make_float4(out[0], out[1], out[2], out[3]);
            dst4[1] = make_float4(out[4], out[5], out[6], out[7]);
        } else {
            __half2* hdst = (__half2*)(g_hf + (size_t)wid * HIDD + lane * 8);
            hdst[0] = __floats2half2_rn(out[0], out[1]);
            hdst[1] = __floats2half2_rn(out[2], out[3]);
            hdst[2] = __floats2half2_rn(out[4], out[5]);
            hdst[3] = __floats2half2_rn(out[6], out[7]);
        }
    }
}

// thread handles channel c over 16 consecutive (batch-sorted) nodes; run-length merge
__global__ void k_pool() {
    int i = blockIdx.x * blockDim.x + threadIdx.x;
    int c = i & 63;
    int n0 = (i >> 6) * 16;
    if (n0 >= NN) return;
    float run = 0.f; float cnt = 0.f; int gcur = -1;
#pragma unroll
    for (int t = 0; t < 16; t++) {
        int n = n0 + t;
        if (n >= NN) break;
        int g = g_batch[n];
        if (g != gcur) {
            if (gcur >= 0) {
                atomicAdd(&g_pool[gcur * HIDD + c], run);
                if (c == 0) atomicAdd(&g_cnt[gcur], cnt);
            }
            gcur = g; run = 0.f; cnt = 0.f;
        }
        run += g_h[n * HIDD + c];
        cnt += 1.f;
    }
    if (gcur >= 0) {
        atomicAdd(&g_pool[gcur * HIDD + c], run);
        if (c == 0) atomicAdd(&g_cnt[gcur], cnt);
    }
}

__global__ void k_final(const float* __restrict__ Wout, const float* __restrict__ bout,
                        float* __restrict__ out) {
    int g = threadIdx.x;
    if (g >= GG) return;
    float cnt = fmaxf(g_cnt[g], 1.f);
    float s = 0.f;
#pragma unroll
    for (int c = 0; c < HIDD; c++) s += (g_pool[g * HIDD + c] / cnt) * Wout[c];
    out[g] = 1.f / (1.f + expf(-(s + bout[0])));
}

// ---------------- launch ----------------
extern "C" void kernel_launch(void* const* d_in, const int* in_sizes, int n_in,
                              void* d_out, int out_size) {
    int ix, iei, ib, iwin, ibin, iwout, ibout, iw[3], ias[3], iad[3], ibg[3];
    if (n_in >= 2 && in_sizes[1] == 2 * EE) {
        ix = 0; iei = 1; ib = 2; iwin = 3; ibin = 4; iwout = 5; ibout = 6;
        for (int l = 0; l < 3; l++) { iw[l] = 7 + 4 * l; ias[l] = 8 + 4 * l; iad[l] = 9 + 4 * l; ibg[l] = 10 + 4 * l; }
    } else {
        ix = 0; iwin = 1; ibin = 2;
        for (int l = 0; l < 3; l++) { iw[l] = 3 + 4 * l; ias[l] = 4 + 4 * l; iad[l] = 5 + 4 * l; ibg[l] = 6 + 4 * l; }
        iwout = 15; ibout = 16; iei = 17; ib = 18;
    }

    const float* x     = (const float*)d_in[ix];
    const void*  ei    = d_in[iei];
    const void*  batch = d_in[ib];
    const float* W_in  = (const float*)d_in[iwin];
    const float* b_in  = (const float*)d_in[ibin];
    const float* W_out = (const float*)d_in[iwout];
    const float* b_out = (const float*)d_in[ibout];
    float* out = (float*)d_out;

    // lazily-created streams + events (first call = correctness run, uncaptured)
    static cudaStream_t s1 = nullptr, s2 = nullptr;
    static cudaEvent_t eFork, eW0, eW1, eW2, eFill;
    if (!s1) {
        cudaStreamCreateWithFlags(&s1, cudaStreamNonBlocking);
        cudaStreamCreateWithFlags(&s2, cudaStreamNonBlocking);
        cudaEventCreateWithFlags(&eFork, cudaEventDisableTiming);
        cudaEventCreateWithFlags(&eW0,   cudaEventDisableTiming);
        cudaEventCreateWithFlags(&eW1,   cudaEventDisableTiming);
        cudaEventCreateWithFlags(&eW2,   cudaEventDisableTiming);
        cudaEventCreateWithFlags(&eFill, cudaEventDisableTiming);
    }

    const int T = 256;
    auto gsz = [](long long n, int t) { return (int)((n + t - 1) / t); };
    const int WPG = gsz(KP * HC + 256 + NHEAD, T);

    // fork both side streams
    cudaEventRecord(eFork, 0);
    cudaStreamWaitEvent(s1, eFork, 0);
    cudaStreamWaitEvent(s2, eFork, 0);

    // s1: CSR build chain only (critical path to gather0)
    k_zero<<<gsz(NN, T), T, 0, s1>>>();
    k_deg<<<gsz(EE, T), T, 0, s1>>>(ei, batch);
    k_scan1<<<SCAN_NBLK, SCAN_B, 0, s1>>>();
    k_scanfix<<<gsz(NN, T), T, 0, s1>>>();
    k_fill<<<gsz(ELNUM, T), T, 0, s1>>>(ei);
    cudaEventRecord(eFill, s1);

    // s2: weight packs (small)
    k_wpack<<<WPG, T, 0, s2>>>((const float*)d_in[iw[0]], (const float*)d_in[ias[0]],
                               (const float*)d_in[iad[0]], 0);
    cudaEventRecord(eW0, s2);
    k_wpack<<<WPG, T, 0, s2>>>((const float*)d_in[iw[1]], (const float*)d_in[ias[1]],
                               (const float*)d_in[iad[1]], 1);
    cudaEventRecord(eW1, s2);
    k_wpack<<<WPG, T, 0, s2>>>((const float*)d_in[iw[2]], (const float*)d_in[ias[2]],
                               (const float*)d_in[iad[2]], 2);
    cudaEventRecord(eW2, s2);

    // main stream: node pipeline
    k_lin_in<<<gsz((long long)NN * HIDD, T), T>>>(x, W_in, b_in);
    cudaStreamWaitEvent(0, eW0, 0);
    k_mma<<<MMA_GRID, 256>>>(0);
    cudaStreamWaitEvent(0, eFill, 0);
    k_attn_gather<0><<<gsz((long long)NN * 32, T), T>>>((const float*)d_in[ibg[0]], 0);

    cudaStreamWaitEvent(0, eW1, 0);
    k_mma<<<MMA_GRID, 256>>>(1);
    k_attn_gather<0><<<gsz((long long)NN * 32, T), T>>>((const float*)d_in[ibg[1]], 1);

    cudaStreamWaitEvent(0, eW2, 0);
    k_mma<<<MMA_GRID, 256>>>(2);
    k_attn_gather<1><<<gsz((long long)NN * 32, T), T>>>((const float*)d_in[ibg[2]], 2);

    k_pool<<<gsz((long long)((NN + 15) / 16) * HIDD, T), T>>>();
    k_final<<<1, 64>>>(W_out, b_out, out);
}